// round 16
// baseline (speedup 1.0000x reference)
#include <cuda_runtime.h>
#include <cuda_fp16.h>
#include <math.h>
#include <stdint.h>

// ---------------------------------------------------------------------------
// BailingMoeV2Gate (plain sm_103 target, no tcgen05):
// logits = X[T,4096] @ W[256,4096]^T via mma.sync.m16n8k16 fp16 2-way split,
// 3 products {x0w0, x0w1, x1w0}. W pre-scaled by 2^12, X by 2^4; epilogue
// x 2^-16. One 6-mma chain per 32-k stage (C=0 seeded) + Kahan RN master add
// -- accumulation order bit-identical to the R13 passing kernel.
// R16: tile M=128 x N=64, 256 threads, __launch_bounds__(256,2) -> TWO CTAs
// per SM; barrier stalls of one CTA overlap with the other's issue
// (R15 ncu: tensor 28%, occ 24.9%, issue 39% -> latency-bound at occ 1).
// Output (fp32 concat): [T*8] idx, [T*8] weights, [T*256] logits.
// ---------------------------------------------------------------------------

#define HID   4096
#define NEXP  256
#define KC    32
#define NST   (HID / KC)   // 128 stages

__device__ float g_logits_scratch[16384 * 256];
__device__ __half g_W0[NEXP * HID];   // fp16(W * 4096)
__device__ __half g_W1[NEXP * HID];   // fp16 residual

__device__ __forceinline__ uint32_t smem_u32(const void* p) {
    uint32_t a;
    asm("{ .reg .u64 t; cvta.to.shared.u64 t, %1; cvt.u32.u64 %0, t; }"
        : "=r"(a) : "l"(p));
    return a;
}

#define MMA_INIT(d, a, b)                                                  \
    asm volatile(                                                          \
        "mma.sync.aligned.m16n8k16.row.col.f32.f16.f16.f32 "               \
        "{%0,%1,%2,%3}, {%4,%5,%6,%7}, {%8,%9}, {%10,%11,%12,%13};"        \
        : "=f"((d)[0]), "=f"((d)[1]), "=f"((d)[2]), "=f"((d)[3])           \
        : "r"((a)[0]), "r"((a)[1]), "r"((a)[2]), "r"((a)[3]),              \
          "r"((b)[0]), "r"((b)[1]),                                        \
          "f"(0.0f), "f"(0.0f), "f"(0.0f), "f"(0.0f))

#define MMA_ACC(d, a, b)                                                   \
    asm volatile(                                                          \
        "mma.sync.aligned.m16n8k16.row.col.f32.f16.f16.f32 "               \
        "{%0,%1,%2,%3}, {%4,%5,%6,%7}, {%8,%9}, {%0,%1,%2,%3};"            \
        : "+f"((d)[0]), "+f"((d)[1]), "+f"((d)[2]), "+f"((d)[3])           \
        : "r"((a)[0]), "r"((a)[1]), "r"((a)[2]), "r"((a)[3]),              \
          "r"((b)[0]), "r"((b)[1]))

#define LDMATRIX_X4(r, addr)                                               \
    asm volatile("ldmatrix.sync.aligned.m8n8.x4.shared.b16 "               \
                 "{%0,%1,%2,%3}, [%4];"                                    \
                 : "=r"((r)[0]), "=r"((r)[1]), "=r"((r)[2]), "=r"((r)[3])  \
                 : "r"(addr))

#define LDMATRIX_X2(r, addr)                                               \
    asm volatile("ldmatrix.sync.aligned.m8n8.x2.shared.b16 {%0,%1}, [%2];" \
                 : "=r"((r)[0]), "=r"((r)[1]) : "r"(addr))

#define CP_ASYNC16(dst, src)                                               \
    asm volatile("{ .reg .u64 g; cvta.to.global.u64 g, %1; "               \
                 "cp.async.ca.shared.global [%0], [g], 16; }"              \
                 :: "r"(dst), "l"(src))

// ====================== W split pre-kernel =================================
__global__ __launch_bounds__(256) void wsplit_kernel(const float* __restrict__ W) {
    size_t i = ((size_t)blockIdx.x * 256 + threadIdx.x) * 4;
    float4 v = *(const float4*)(W + i);
    float a[4] = {v.x, v.y, v.z, v.w};
#pragma unroll
    for (int j = 0; j < 4; j++) {
        float x = a[j] * 4096.0f;
        __half w0 = __float2half_rn(x);
        float r1 = x - __half2float(w0);
        __half w1 = __float2half_rn(r1);
        g_W0[i + j] = w0;
        g_W1[i + j] = w1;
    }
}

// ====================== split-fp16 mma.sync GEMM ===========================
// Grid (4, T/128): CTA tile M=128, N=64. 256 threads = 8 warps (4M x 2N),
// warp tile 32x32. KC=32 (2 k16 steps), 2-stage double buffer, occupancy 2.
// SMEM fp16 tiles, 80B padded row stride (64B data + 16B pad).
#define A_ROW    80
#define A_SPLIT  (128 * A_ROW)       // 10240
#define A_BUF    (2 * A_SPLIT)       // 20480 (2 splits, one stage buffer)
#define B_OFF    (2 * A_BUF)         // 40960
#define B_SPLIT  (64 * A_ROW)        // 5120
#define B_BUF    (2 * B_SPLIT)       // 10240
#define GEMM_SMEM (B_OFF + 2 * B_BUF)  // 61440 -> 2 CTAs/SM

__global__ void __launch_bounds__(256, 2) gemm_fp16_split(
    const float* __restrict__ X, float* __restrict__ C)
{
    extern __shared__ char smem[];
    const uint32_t sb = smem_u32(smem);
    const int tid  = threadIdx.x;
    const int lane = tid & 31;
    const int wid  = tid >> 5;
    const int wm   = wid >> 1;      // 0..3 (M)
    const int wn   = wid & 1;       // 0..1 (N)
    const int bm   = blockIdx.y * 128;
    const int bn   = blockIdx.x * 64;

    // ---- A loader: 256 threads, 16 floats each: row = tid>>1, half = tid&1
    const int ar  = tid >> 1;
    const int akh = tid & 1;
    const float* aptr = X + (size_t)(bm + ar) * HID + akh * 16;

    // ---- B loader: 2 cp.async 16B chunks per thread per stage ----
    // j = tid*2+c in [0,512): p = j>>8, row = (j&255)>>2, ch = j&3
    const __half* wbase[2] = {g_W0, g_W1};

    float acc[2][4][4], cmp[2][4][4];
#pragma unroll
    for (int m = 0; m < 2; m++)
#pragma unroll
        for (int n = 0; n < 4; n++)
#pragma unroll
            for (int k = 0; k < 4; k++) { acc[m][n][k] = 0.0f; cmp[m][n][k] = 0.0f; }

    float4 xs0, xs1, xs2, xs3;   // 16 staged fp32

    auto a_ldg = [&](int s) {
        const float* p = aptr + s * KC;
        xs0 = *(const float4*)(p);
        xs1 = *(const float4*)(p + 4);
        xs2 = *(const float4*)(p + 8);
        xs3 = *(const float4*)(p + 12);
    };
    auto b_cpasync = [&](int s, int b) {
#pragma unroll
        for (int c = 0; c < 2; c++) {
            int j   = tid * 2 + c;
            int p   = j >> 8;
            int rem = j & 255;
            int row = rem >> 2;
            int ch  = rem & 3;
            const char* src = (const char*)(wbase[p] + (size_t)(bn + row) * HID + s * KC) + ch * 16;
            uint32_t dst = sb + B_OFF + b * B_BUF + p * B_SPLIT + row * A_ROW + ch * 16;
            CP_ASYNC16(dst, src);
        }
        asm volatile("cp.async.commit_group;" ::: "memory");
    };
    auto a_sts = [&](int b) {
        float xv[16] = {xs0.x, xs0.y, xs0.z, xs0.w, xs1.x, xs1.y, xs1.z, xs1.w,
                        xs2.x, xs2.y, xs2.z, xs2.w, xs3.x, xs3.y, xs3.z, xs3.w};
        __half2 h0[8], h1[8];
#pragma unroll
        for (int i = 0; i < 8; i++) {
            float xa = xv[2 * i] * 16.0f;       // exact scale
            float xb = xv[2 * i + 1] * 16.0f;
            __half a0 = __float2half_rn(xa);
            float ra = xa - __half2float(a0);
            __half a1 = __float2half_rn(ra);
            __half b0 = __float2half_rn(xb);
            float rb = xb - __half2float(b0);
            __half b1 = __float2half_rn(rb);
            h0[i] = __half2(a0, b0);
            h1[i] = __half2(a1, b1);
        }
        char* base = smem + b * A_BUF + ar * A_ROW + akh * 32;
        *(uint4*)(base)                = ((const uint4*)h0)[0];
        *(uint4*)(base + 16)           = ((const uint4*)h0)[1];
        *(uint4*)(base + A_SPLIT)      = ((const uint4*)h1)[0];
        *(uint4*)(base + A_SPLIT + 16) = ((const uint4*)h1)[1];
    };

    // ---- ldmatrix addresses ----
    // A x4 (one m16 x k16 frag): mt = lane>>3: row (lane&7)+8*(mt&1), khalf mt>>1
    const int a_mt = lane >> 3;
    const uint32_t a_addr0 = sb + (wm * 32 + (lane & 7) + ((a_mt & 1) << 3)) * A_ROW
                           + (a_mt >> 1) * 16;
    // B x2: lanes 0-15: rows n = (l15&7), k-half = (l15>>3)*16
    const int l15 = lane & 15;
    const uint32_t b_addr0 = sb + B_OFF + (wn * 32 + (l15 & 7)) * A_ROW
                           + (l15 >> 3) * 16;

    auto compute = [&](int b) {
        uint32_t af[2][2][2][4];   // [split][m][kk][frag]
#pragma unroll
        for (int p = 0; p < 2; p++)
#pragma unroll
            for (int m = 0; m < 2; m++)
#pragma unroll
                for (int kk = 0; kk < 2; kk++)
                    LDMATRIX_X4(af[p][m][kk],
                        a_addr0 + b * A_BUF + p * A_SPLIT + m * 16 * A_ROW + kk * 32);
#pragma unroll
        for (int nt = 0; nt < 4; nt++) {
            uint32_t bf[2][2][2];  // [split][kk][frag]
#pragma unroll
            for (int p = 0; p < 2; p++)
#pragma unroll
                for (int kk = 0; kk < 2; kk++)
                    LDMATRIX_X2(bf[p][kk],
                        b_addr0 + b * B_BUF + p * B_SPLIT + nt * 8 * A_ROW + kk * 32);
#pragma unroll
            for (int m = 0; m < 2; m++) {
                float ch[4];       // one 6-mma chain per stage (C=0 seeded)
                MMA_INIT(ch, af[0][m][0], bf[0][0]);   // x0*w0 kk0
                MMA_ACC (ch, af[0][m][0], bf[1][0]);   // x0*w1 kk0
                MMA_ACC (ch, af[1][m][0], bf[0][0]);   // x1*w0 kk0
                MMA_ACC (ch, af[0][m][1], bf[0][1]);   // x0*w0 kk1
                MMA_ACC (ch, af[0][m][1], bf[1][1]);   // x0*w1 kk1
                MMA_ACC (ch, af[1][m][1], bf[0][1]);   // x1*w0 kk1
#pragma unroll
                for (int k = 0; k < 4; k++) {          // Kahan master add (RN)
                    float y = __fadd_rn(ch[k], -cmp[m][nt][k]);
                    float t = __fadd_rn(acc[m][nt][k], y);
                    cmp[m][nt][k] = __fadd_rn(__fadd_rn(t, -acc[m][nt][k]), -y);
                    acc[m][nt][k] = t;
                }
            }
        }
    };

    // ---- prologue ----
    a_ldg(0);
    b_cpasync(0, 0);
    a_sts(0);
    asm volatile("cp.async.wait_group 0;" ::: "memory");
    __syncthreads();

    // ---- mainloop ----
    for (int s = 0; s < NST; s++) {
        const int b = s & 1;
        const bool more = (s + 1 < NST);
        if (more) {
            a_ldg(s + 1);
            b_cpasync(s + 1, b ^ 1);
        }
        compute(b);
        if (more) a_sts(b ^ 1);
        asm volatile("cp.async.wait_group 0;" ::: "memory");
        __syncthreads();
    }

    // ---- epilogue: undo 2^16 scaling (exact) ----
    const float SC = 1.0f / 65536.0f;
#pragma unroll
    for (int m = 0; m < 2; m++) {
#pragma unroll
        for (int nt = 0; nt < 4; nt++) {
            const int row = bm + wm * 32 + m * 16 + (lane >> 2);
            const int col = bn + wn * 32 + nt * 8 + ((lane & 3) << 1);
            float* cp = C + (size_t)row * NEXP + col;
            *(float2*)cp = make_float2(acc[m][nt][0] * SC, acc[m][nt][1] * SC);
            *(float2*)(cp + 8 * NEXP) = make_float2(acc[m][nt][2] * SC, acc[m][nt][3] * SC);
        }
    }
}

// ======================== routing: one warp per token =======================
__global__ __launch_bounds__(256) void routing_kernel(
    const float* __restrict__ logits, const float* __restrict__ bias,
    float* __restrict__ out_idx, float* __restrict__ out_w, int T)
{
    const int wip  = threadIdx.x >> 5;
    const int lane = threadIdx.x & 31;
    const int t = blockIdx.x * 8 + wip;
    if (t >= T) return;

    __shared__ float s_sc[8][256];
    __shared__ float s_sr[8][256];
    __shared__ float s_gv[8][8];
    __shared__ int   s_gi[8][8];

    float* sc = s_sc[wip];
    float* sr = s_sr[wip];
    const float* lrow = logits + (size_t)t * 256;

#pragma unroll
    for (int i = 0; i < 8; i++) {
        int e = i * 32 + lane;
        float l = lrow[e];
        float s = 1.0f / (1.0f + expf(-l));
        sc[e] = s;
        sr[e] = s + bias[e];
    }
    __syncwarp();

    float gscore = -INFINITY;
    if (lane < 8) {
        float m1 = -INFINITY, m2 = -INFINITY;
#pragma unroll
        for (int j = 0; j < 32; j++) {
            float v = sr[lane * 32 + ((j + lane * 4) & 31)];
            if (v > m1) { m2 = m1; m1 = v; }
            else if (v > m2) { m2 = v; }
        }
        gscore = m1 + m2;
    }

    float gs[8];
#pragma unroll
    for (int g = 0; g < 8; g++) gs[g] = __shfl_sync(0xffffffffu, gscore, g);
    unsigned gmask = 0;
#pragma unroll
    for (int k = 0; k < 4; k++) {
        int bi = -1; float bv = -INFINITY;
#pragma unroll
        for (int g = 0; g < 8; g++) {
            bool taken = (gmask >> g) & 1u;
            if (!taken && gs[g] > bv) { bv = gs[g]; bi = g; }
        }
        gmask |= 1u << bi;
    }

    float vals[8];
#pragma unroll
    for (int i = 0; i < 8; i++)
        vals[i] = ((gmask >> i) & 1u) ? sr[i * 32 + lane] : -INFINITY;

    float sum = 0.0f;
    for (int k = 0; k < 8; k++) {
        float bv = -INFINITY; int bi = 0x7fffffff;
#pragma unroll
        for (int i = 0; i < 8; i++) {
            int e = i * 32 + lane;
            if (vals[i] > bv || (vals[i] == bv && e < bi)) { bv = vals[i]; bi = e; }
        }
#pragma unroll
        for (int off = 16; off; off >>= 1) {
            float ov = __shfl_xor_sync(0xffffffffu, bv, off);
            int   oi = __shfl_xor_sync(0xffffffffu, bi, off);
            if (ov > bv || (ov == bv && oi < bi)) { bv = ov; bi = oi; }
        }
        if ((bi & 31) == lane) vals[bi >> 5] = -INFINITY;
        float g = sc[bi];
        sum += g;
        if (lane == 0) { s_gv[wip][k] = g; s_gi[wip][k] = bi; }
    }
    __syncwarp();

    if (lane < 8) {
        float w = s_gv[wip][lane] / (sum + 1e-20f) * 2.5f;
        out_w[(size_t)t * 8 + lane]   = w;
        out_idx[(size_t)t * 8 + lane] = (float)s_gi[wip][lane];
    }
}

// ============================== launch ======================================
extern "C" void kernel_launch(void* const* d_in, const int* in_sizes, int n_in,
                              void* d_out, int out_size)
{
    const float* X    = (const float*)d_in[0];  // [T, H]
    const float* W    = (const float*)d_in[1];  // [E, H]
    const float* bias = (const float*)d_in[2];  // [E]

    const int E = in_sizes[2];
    const int H = in_sizes[1] / E;
    const int T = in_sizes[0] / H;

    float* out     = (float*)d_out;
    float* out_idx = out;
    float* out_w   = out + (size_t)T * 8;

    float* logits;
    if ((size_t)out_size >= (size_t)T * 16 + (size_t)T * E) {
        logits = out + (size_t)T * 16;
    } else {
        float* p;
        cudaGetSymbolAddress((void**)&p, g_logits_scratch);
        logits = p;
    }

    // 1) W -> two fp16 split arrays (scaled by 2^12)
    wsplit_kernel<<<(E * H / 4 + 255) / 256, 256>>>(W);

    // 2) tensor-core split GEMM -> logits (M=128 x N=64, occupancy 2)
    cudaFuncSetAttribute(gemm_fp16_split,
                         cudaFuncAttributeMaxDynamicSharedMemorySize, GEMM_SMEM);
    dim3 grid(E / 64, T / 128);
    gemm_fp16_split<<<grid, 256, GEMM_SMEM>>>(X, logits);

    // 3) routing
    routing_kernel<<<(T + 7) / 8, 256>>>(logits, bias, out_idx, out_w, T);
}

// round 17
// speedup vs baseline: 1.3904x; 1.3904x over previous
#include <cuda_runtime.h>
#include <cuda_fp16.h>
#include <math.h>
#include <stdint.h>

// ---------------------------------------------------------------------------
// BailingMoeV2Gate (plain sm_103 target, no tcgen05):
// logits = X[T,4096] @ W[256,4096]^T via mma.sync.m16n8k16 fp16 2-way split,
// 3 products {x0w0, x0w1, x1w0}. W pre-scaled by 2^12, X by 2^4; epilogue
// x 2^-16. One 6-mma chain per 32-k stage (C=0 seeded), PLAIN RN fp32 master
// accumulation (R7 scheme) -- frees the Kahan cmp registers so the 128x128
// CTA fits at OCCUPANCY 2 (256 thr, <=128 regs, 80KB smem x2 = 160KB).
// R15 ncu: occ 24.9%, issue 39%, tensor 28% -> latency-bound at occ 1;
// second resident CTA fills the idle issue slots.
// Output (fp32 concat): [T*8] idx, [T*8] weights, [T*256] logits.
// ---------------------------------------------------------------------------

#define HID   4096
#define NEXP  256
#define KC    32
#define NST   (HID / KC)   // 128 stages

__device__ float g_logits_scratch[16384 * 256];
__device__ __half g_W0[NEXP * HID];   // fp16(W * 4096)
__device__ __half g_W1[NEXP * HID];   // fp16 residual

__device__ __forceinline__ uint32_t smem_u32(const void* p) {
    uint32_t a;
    asm("{ .reg .u64 t; cvta.to.shared.u64 t, %1; cvt.u32.u64 %0, t; }"
        : "=r"(a) : "l"(p));
    return a;
}

#define MMA_INIT(d, a, b)                                                  \
    asm volatile(                                                          \
        "mma.sync.aligned.m16n8k16.row.col.f32.f16.f16.f32 "               \
        "{%0,%1,%2,%3}, {%4,%5,%6,%7}, {%8,%9}, {%10,%11,%12,%13};"        \
        : "=f"((d)[0]), "=f"((d)[1]), "=f"((d)[2]), "=f"((d)[3])           \
        : "r"((a)[0]), "r"((a)[1]), "r"((a)[2]), "r"((a)[3]),              \
          "r"((b)[0]), "r"((b)[1]),                                        \
          "f"(0.0f), "f"(0.0f), "f"(0.0f), "f"(0.0f))

#define MMA_ACC(d, a, b)                                                   \
    asm volatile(                                                          \
        "mma.sync.aligned.m16n8k16.row.col.f32.f16.f16.f32 "               \
        "{%0,%1,%2,%3}, {%4,%5,%6,%7}, {%8,%9}, {%0,%1,%2,%3};"            \
        : "+f"((d)[0]), "+f"((d)[1]), "+f"((d)[2]), "+f"((d)[3])           \
        : "r"((a)[0]), "r"((a)[1]), "r"((a)[2]), "r"((a)[3]),              \
          "r"((b)[0]), "r"((b)[1]))

#define LDMATRIX_X4(r, addr)                                               \
    asm volatile("ldmatrix.sync.aligned.m8n8.x4.shared.b16 "               \
                 "{%0,%1,%2,%3}, [%4];"                                    \
                 : "=r"((r)[0]), "=r"((r)[1]), "=r"((r)[2]), "=r"((r)[3])  \
                 : "r"(addr))

#define LDMATRIX_X2(r, addr)                                               \
    asm volatile("ldmatrix.sync.aligned.m8n8.x2.shared.b16 {%0,%1}, [%2];" \
                 : "=r"((r)[0]), "=r"((r)[1]) : "r"(addr))

#define CP_ASYNC16(dst, src)                                               \
    asm volatile("{ .reg .u64 g; cvta.to.global.u64 g, %1; "               \
                 "cp.async.ca.shared.global [%0], [g], 16; }"              \
                 :: "r"(dst), "l"(src))

// ====================== W split pre-kernel =================================
__global__ __launch_bounds__(256) void wsplit_kernel(const float* __restrict__ W) {
    size_t i = ((size_t)blockIdx.x * 256 + threadIdx.x) * 4;
    float4 v = *(const float4*)(W + i);
    float a[4] = {v.x, v.y, v.z, v.w};
#pragma unroll
    for (int j = 0; j < 4; j++) {
        float x = a[j] * 4096.0f;
        __half w0 = __float2half_rn(x);
        float r1 = x - __half2float(w0);
        __half w1 = __float2half_rn(r1);
        g_W0[i + j] = w0;
        g_W1[i + j] = w1;
    }
}

// ====================== split-fp16 mma.sync GEMM ===========================
// Grid (2, T/128): CTA tile M=128, N=128. 256 threads = 8 warps (4M x 2N),
// warp tile 32x64. KC=32 (2 k16 steps), 2-stage double buffer, OCC 2.
// SMEM fp16 tiles, 80B padded row stride (64B data + 16B pad).
#define A_ROW    80
#define A_SPLIT  (128 * A_ROW)       // 10240
#define A_BUF    (2 * A_SPLIT)       // 20480 (2 splits, one stage buffer)
#define B_OFF    (2 * A_BUF)         // 40960
#define B_SPLIT  (128 * A_ROW)
#define B_BUF    (2 * B_SPLIT)
#define GEMM_SMEM (B_OFF + 2 * B_BUF)  // 81920 -> 2 CTAs/SM (160KB)

__global__ void __launch_bounds__(256, 2) gemm_fp16_split(
    const float* __restrict__ X, float* __restrict__ C)
{
    extern __shared__ char smem[];
    const uint32_t sb = smem_u32(smem);
    const int tid  = threadIdx.x;
    const int lane = tid & 31;
    const int wid  = tid >> 5;
    const int wm   = wid >> 1;      // 0..3 (M)
    const int wn   = wid & 1;       // 0..1 (N)
    const int bm   = blockIdx.y * 128;
    const int bn   = blockIdx.x * 128;

    // ---- A loader: 256 threads, 16 floats each: row = tid>>1, half = tid&1
    const int ar  = tid >> 1;
    const int akh = tid & 1;
    const float* aptr = X + (size_t)(bm + ar) * HID + akh * 16;

    // ---- B loader: 4 cp.async 16B chunks per thread per stage ----
    // j = tid*4+c in [0,1024): p = j>>9, row = (j&511)>>2, ch = j&3
    const __half* wbase[2] = {g_W0, g_W1};

    float acc[2][8][4];
#pragma unroll
    for (int m = 0; m < 2; m++)
#pragma unroll
        for (int n = 0; n < 8; n++)
#pragma unroll
            for (int k = 0; k < 4; k++) acc[m][n][k] = 0.0f;

    float4 xs0, xs1, xs2, xs3;   // 16 staged fp32

    auto a_ldg = [&](int s) {
        const float* p = aptr + s * KC;
        xs0 = *(const float4*)(p);
        xs1 = *(const float4*)(p + 4);
        xs2 = *(const float4*)(p + 8);
        xs3 = *(const float4*)(p + 12);
    };
    auto b_cpasync = [&](int s, int b) {
#pragma unroll
        for (int c = 0; c < 4; c++) {
            int j   = tid * 4 + c;
            int p   = j >> 9;
            int rem = j & 511;
            int row = rem >> 2;
            int ch  = rem & 3;
            const char* src = (const char*)(wbase[p] + (size_t)(bn + row) * HID + s * KC) + ch * 16;
            uint32_t dst = sb + B_OFF + b * B_BUF + p * B_SPLIT + row * A_ROW + ch * 16;
            CP_ASYNC16(dst, src);
        }
        asm volatile("cp.async.commit_group;" ::: "memory");
    };
    auto a_sts = [&](int b) {
        float xv[16] = {xs0.x, xs0.y, xs0.z, xs0.w, xs1.x, xs1.y, xs1.z, xs1.w,
                        xs2.x, xs2.y, xs2.z, xs2.w, xs3.x, xs3.y, xs3.z, xs3.w};
        __half2 h0[8], h1[8];
#pragma unroll
        for (int i = 0; i < 8; i++) {
            float xa = xv[2 * i] * 16.0f;       // exact scale
            float xb = xv[2 * i + 1] * 16.0f;
            __half a0 = __float2half_rn(xa);
            float ra = xa - __half2float(a0);
            __half a1 = __float2half_rn(ra);
            __half b0 = __float2half_rn(xb);
            float rb = xb - __half2float(b0);
            __half b1 = __float2half_rn(rb);
            h0[i] = __half2(a0, b0);
            h1[i] = __half2(a1, b1);
        }
        char* base = smem + b * A_BUF + ar * A_ROW + akh * 32;
        *(uint4*)(base)                = ((const uint4*)h0)[0];
        *(uint4*)(base + 16)           = ((const uint4*)h0)[1];
        *(uint4*)(base + A_SPLIT)      = ((const uint4*)h1)[0];
        *(uint4*)(base + A_SPLIT + 16) = ((const uint4*)h1)[1];
    };

    // ---- ldmatrix addresses ----
    const int a_mt = lane >> 3;
    const uint32_t a_addr0 = sb + (wm * 32 + (lane & 7) + ((a_mt & 1) << 3)) * A_ROW
                           + (a_mt >> 1) * 16;
    const int l15 = lane & 15;
    const uint32_t b_addr0 = sb + B_OFF + (wn * 64 + (l15 & 7)) * A_ROW
                           + (l15 >> 3) * 16;

    auto compute = [&](int b) {
        uint32_t af[2][2][2][4];   // [split][m][kk][frag]
#pragma unroll
        for (int p = 0; p < 2; p++)
#pragma unroll
            for (int m = 0; m < 2; m++)
#pragma unroll
                for (int kk = 0; kk < 2; kk++)
                    LDMATRIX_X4(af[p][m][kk],
                        a_addr0 + b * A_BUF + p * A_SPLIT + m * 16 * A_ROW + kk * 32);
#pragma unroll
        for (int nt = 0; nt < 8; nt++) {
            uint32_t bf[2][2][2];  // [split][kk][frag]
#pragma unroll
            for (int p = 0; p < 2; p++)
#pragma unroll
                for (int kk = 0; kk < 2; kk++)
                    LDMATRIX_X2(bf[p][kk],
                        b_addr0 + b * B_BUF + p * B_SPLIT + nt * 8 * A_ROW + kk * 32);
#pragma unroll
            for (int m = 0; m < 2; m++) {
                float ch[4];       // one 6-mma chain per stage (C=0 seeded)
                MMA_INIT(ch, af[0][m][0], bf[0][0]);   // x0*w0 kk0
                MMA_ACC (ch, af[0][m][0], bf[1][0]);   // x0*w1 kk0
                MMA_ACC (ch, af[1][m][0], bf[0][0]);   // x1*w0 kk0
                MMA_ACC (ch, af[0][m][1], bf[0][1]);   // x0*w0 kk1
                MMA_ACC (ch, af[0][m][1], bf[1][1]);   // x0*w1 kk1
                MMA_ACC (ch, af[1][m][1], bf[0][1]);   // x1*w0 kk1
#pragma unroll
                for (int k = 0; k < 4; k++)            // plain RN master add
                    acc[m][nt][k] = __fadd_rn(acc[m][nt][k], ch[k]);
            }
        }
    };

    // ---- prologue ----
    a_ldg(0);
    b_cpasync(0, 0);
    a_sts(0);
    asm volatile("cp.async.wait_group 0;" ::: "memory");
    __syncthreads();

    // ---- mainloop ----
    for (int s = 0; s < NST; s++) {
        const int b = s & 1;
        const bool more = (s + 1 < NST);
        if (more) {
            a_ldg(s + 1);
            b_cpasync(s + 1, b ^ 1);
        }
        compute(b);
        if (more) a_sts(b ^ 1);
        asm volatile("cp.async.wait_group 0;" ::: "memory");
        __syncthreads();
    }

    // ---- epilogue: undo 2^16 scaling (exact) ----
    const float SC = 1.0f / 65536.0f;
#pragma unroll
    for (int m = 0; m < 2; m++) {
#pragma unroll
        for (int nt = 0; nt < 8; nt++) {
            const int row = bm + wm * 32 + m * 16 + (lane >> 2);
            const int col = bn + wn * 64 + nt * 8 + ((lane & 3) << 1);
            float* cp = C + (size_t)row * NEXP + col;
            *(float2*)cp = make_float2(acc[m][nt][0] * SC, acc[m][nt][1] * SC);
            *(float2*)(cp + 8 * NEXP) = make_float2(acc[m][nt][2] * SC, acc[m][nt][3] * SC);
        }
    }
}

// ======================== routing: one warp per token =======================
__global__ __launch_bounds__(256) void routing_kernel(
    const float* __restrict__ logits, const float* __restrict__ bias,
    float* __restrict__ out_idx, float* __restrict__ out_w, int T)
{
    const int wip  = threadIdx.x >> 5;
    const int lane = threadIdx.x & 31;
    const int t = blockIdx.x * 8 + wip;
    if (t >= T) return;

    __shared__ float s_sc[8][256];
    __shared__ float s_sr[8][256];
    __shared__ float s_gv[8][8];
    __shared__ int   s_gi[8][8];

    float* sc = s_sc[wip];
    float* sr = s_sr[wip];
    const float* lrow = logits + (size_t)t * 256;

#pragma unroll
    for (int i = 0; i < 8; i++) {
        int e = i * 32 + lane;
        float l = lrow[e];
        float s = 1.0f / (1.0f + expf(-l));
        sc[e] = s;
        sr[e] = s + bias[e];
    }
    __syncwarp();

    float gscore = -INFINITY;
    if (lane < 8) {
        float m1 = -INFINITY, m2 = -INFINITY;
#pragma unroll
        for (int j = 0; j < 32; j++) {
            float v = sr[lane * 32 + ((j + lane * 4) & 31)];
            if (v > m1) { m2 = m1; m1 = v; }
            else if (v > m2) { m2 = v; }
        }
        gscore = m1 + m2;
    }

    float gs[8];
#pragma unroll
    for (int g = 0; g < 8; g++) gs[g] = __shfl_sync(0xffffffffu, gscore, g);
    unsigned gmask = 0;
#pragma unroll
    for (int k = 0; k < 4; k++) {
        int bi = -1; float bv = -INFINITY;
#pragma unroll
        for (int g = 0; g < 8; g++) {
            bool taken = (gmask >> g) & 1u;
            if (!taken && gs[g] > bv) { bv = gs[g]; bi = g; }
        }
        gmask |= 1u << bi;
    }

    float vals[8];
#pragma unroll
    for (int i = 0; i < 8; i++)
        vals[i] = ((gmask >> i) & 1u) ? sr[i * 32 + lane] : -INFINITY;

    float sum = 0.0f;
    for (int k = 0; k < 8; k++) {
        float bv = -INFINITY; int bi = 0x7fffffff;
#pragma unroll
        for (int i = 0; i < 8; i++) {
            int e = i * 32 + lane;
            if (vals[i] > bv || (vals[i] == bv && e < bi)) { bv = vals[i]; bi = e; }
        }
#pragma unroll
        for (int off = 16; off; off >>= 1) {
            float ov = __shfl_xor_sync(0xffffffffu, bv, off);
            int   oi = __shfl_xor_sync(0xffffffffu, bi, off);
            if (ov > bv || (ov == bv && oi < bi)) { bv = ov; bi = oi; }
        }
        if ((bi & 31) == lane) vals[bi >> 5] = -INFINITY;
        float g = sc[bi];
        sum += g;
        if (lane == 0) { s_gv[wip][k] = g; s_gi[wip][k] = bi; }
    }
    __syncwarp();

    if (lane < 8) {
        float w = s_gv[wip][lane] / (sum + 1e-20f) * 2.5f;
        out_w[(size_t)t * 8 + lane]   = w;
        out_idx[(size_t)t * 8 + lane] = (float)s_gi[wip][lane];
    }
}

// ============================== launch ======================================
extern "C" void kernel_launch(void* const* d_in, const int* in_sizes, int n_in,
                              void* d_out, int out_size)
{
    const float* X    = (const float*)d_in[0];  // [T, H]
    const float* W    = (const float*)d_in[1];  // [E, H]
    const float* bias = (const float*)d_in[2];  // [E]

    const int E = in_sizes[2];
    const int H = in_sizes[1] / E;
    const int T = in_sizes[0] / H;

    float* out     = (float*)d_out;
    float* out_idx = out;
    float* out_w   = out + (size_t)T * 8;

    float* logits;
    if ((size_t)out_size >= (size_t)T * 16 + (size_t)T * E) {
        logits = out + (size_t)T * 16;
    } else {
        float* p;
        cudaGetSymbolAddress((void**)&p, g_logits_scratch);
        logits = p;
    }

    // 1) W -> two fp16 split arrays (scaled by 2^12)
    wsplit_kernel<<<(E * H / 4 + 255) / 256, 256>>>(W);

    // 2) tensor-core split GEMM -> logits (128x128, 256 thr, occupancy 2)
    cudaFuncSetAttribute(gemm_fp16_split,
                         cudaFuncAttributeMaxDynamicSharedMemorySize, GEMM_SMEM);
    dim3 grid(E / 128, T / 128);
    gemm_fp16_split<<<grid, 256, GEMM_SMEM>>>(X, logits);

    // 3) routing
    routing_kernel<<<(T + 7) / 8, 256>>>(logits, bias, out_idx, out_w, T);
}